// round 2
// baseline (speedup 1.0000x reference)
#include <cuda_runtime.h>
#include <math.h>

#define Bb 16
#define Nn 200
#define Dd 128
#define Hh 8
#define ROWS (Bb*Nn)          // 3200
#define NEG_SLOPE 0.2f

// Scratch (static device globals — no allocation)
__device__ float g_buf[ROWS * Dd];      // g = h @ W           (1.6 MB)
__device__ float si_buf[ROWS * Hh];     // s_i
__device__ float sj_buf[ROWS * Hh];     // s_j
__device__ float c1g[Dd * Hh];          // W  folded with a1
__device__ float c2g[Dd * Hh];          // W  folded with a2
__device__ float c3g[Dd * Hh];          // W_e folded with a3

// ---------------------------------------------------------------------------
// Kernel 0: fold W / W_e with the attention vectors a1,a2,a3.
// c{1,2}[d][h] = sum_q W[d, h*16+q] * a{1,2}[q];  c3 from W_e, a3.
// ---------------------------------------------------------------------------
__global__ void precompute_c(const float* __restrict__ W,
                             const float* __restrict__ We,
                             const float* __restrict__ a)
{
    int tid   = threadIdx.x;        // 0..383
    int which = tid >> 7;           // 0: c1, 1: c2, 2: c3
    int d     = tid & 127;
    const float* M  = (which == 2) ? We : W;
    const float* av = a + which * 16;
    float* c = (which == 0) ? c1g : (which == 1) ? c2g : c3g;
    #pragma unroll
    for (int h = 0; h < Hh; h++) {
        float s = 0.f;
        #pragma unroll
        for (int q = 0; q < 16; q++)
            s += M[d * Dd + h * 16 + q] * av[q];
        c[d * Hh + h] = s;
    }
}

// ---------------------------------------------------------------------------
// Kernel 1: g = h @ W  (3200x128 @ 128x128), plus s_i, s_j.
// W staged once per block in 64 KB smem; each block handles 16 rows.
// ---------------------------------------------------------------------------
__global__ void __launch_bounds__(256) gemm_g(const float* __restrict__ h,
                                              const float* __restrict__ W)
{
    extern __shared__ float smem1[];
    float* Wsh = smem1;              // 128*128 floats
    float* hsh = smem1 + Dd * Dd;    // 128 floats
    int tid = threadIdx.x;

    for (int idx = tid; idx < Dd * Dd; idx += 256) Wsh[idx] = W[idx];

    for (int r = 0; r < 16; r++) {
        int row = blockIdx.x * 16 + r;
        __syncthreads();                       // Wsh ready / prev row done
        if (tid < Dd) hsh[tid] = h[(size_t)row * Dd + tid];
        __syncthreads();
        if (tid < Dd) {
            float acc = 0.f;
            #pragma unroll 8
            for (int k = 0; k < Dd; k++)
                acc += hsh[k] * Wsh[k * Dd + tid];
            g_buf[(size_t)row * Dd + tid] = acc;
        } else if (tid < Dd + 16) {
            int t2   = tid - Dd;
            int head = t2 & 7;
            const float* c = (t2 & 8) ? c2g : c1g;
            float acc = 0.f;
            #pragma unroll 4
            for (int d = 0; d < Dd; d++)
                acc += hsh[d] * c[d * Hh + head];
            if (t2 & 8) sj_buf[row * Hh + head] = acc;
            else        si_buf[row * Hh + head] = acc;
        }
    }
}

// ---------------------------------------------------------------------------
// Kernel 2: per (b,i): stream dis_mat row-block, compute s_e (8 heads),
// build masked leaky-relu logits, softmax over j, aggregate out = attn @ g.
// Grid = 3200 blocks (one per (b,i)), 256 threads.
// ---------------------------------------------------------------------------
__global__ void __launch_bounds__(256) attn_kernel(const float* __restrict__ dis,
                                                   const int*   __restrict__ adj,
                                                   float*       __restrict__ out)
{
    __shared__ float esh[Hh * Nn];   // [head][j] logits -> unnormalized probs
    __shared__ float si_sh[Hh];
    __shared__ float inv_sh[Hh];
    __shared__ float outp[Dd];

    int tid  = threadIdx.x;
    int lane = tid & 31;
    int warp = tid >> 5;             // 0..7
    int row  = blockIdx.x;           // b*200 + i
    int b    = row / Nn;

    // Per-lane slice of c3: lane covers d = lane*4 .. lane*4+3, all 8 heads.
    // c3g layout [d][h] -> 32 consecutive floats per lane.
    float c3r[32];
    {
        const float4* cv = (const float4*)c3g;
        #pragma unroll
        for (int t = 0; t < 8; t++)
            ((float4*)c3r)[t] = cv[lane * 8 + t];
    }
    if (tid < Hh) si_sh[tid] = si_buf[row * Hh + tid];
    __syncthreads();

    // ---- Stage 1: s_e + logits. Warp w handles j = w, w+8, ... (25 rows).
    const float4* disv = (const float4*)dis;
    size_t rb = (size_t)row * Nn;
    for (int jj = warp; jj < Nn; jj += 8) {
        float4 dv = disv[(rb + jj) * 32 + lane];
        float v[8];
        #pragma unroll
        for (int h = 0; h < 8; h++)
            v[h] = dv.x * c3r[h] + dv.y * c3r[8 + h]
                 + dv.z * c3r[16 + h] + dv.w * c3r[24 + h];

        // Head-folding butterfly: 9 shuffles instead of 40.
        // After folding bits {4,3,2}, lane holds head (lane>>2)&7.
        float w4[4];
        {
            bool hi = (lane & 16) != 0;
            #pragma unroll
            for (int k = 0; k < 4; k++) {
                float send = hi ? v[k] : v[k + 4];
                float recv = __shfl_xor_sync(0xffffffffu, send, 16);
                w4[k] = (hi ? v[k + 4] : v[k]) + recv;
            }
        }
        float w2[2];
        {
            bool hi = (lane & 8) != 0;
            #pragma unroll
            for (int k = 0; k < 2; k++) {
                float send = hi ? w4[k] : w4[k + 2];
                float recv = __shfl_xor_sync(0xffffffffu, send, 8);
                w2[k] = (hi ? w4[k + 2] : w4[k]) + recv;
            }
        }
        float y;
        {
            bool hi = (lane & 4) != 0;
            float send = hi ? w2[0] : w2[1];
            float recv = __shfl_xor_sync(0xffffffffu, send, 4);
            y = (hi ? w2[1] : w2[0]) + recv;
        }
        y += __shfl_xor_sync(0xffffffffu, y, 1);
        y += __shfl_xor_sync(0xffffffffu, y, 2);

        if ((lane & 3) == 0) {
            int head = lane >> 2;
            float e = si_sh[head]
                    + sj_buf[((size_t)b * Nn + jj) * Hh + head]
                    + y;
            e = (e > 0.f) ? e : NEG_SLOPE * e;          // leaky relu
            if (adj[rb + jj] == 0) e = -INFINITY;       // mask
            esh[head * Nn + jj] = e;
        }
    }
    __syncthreads();

    // ---- Stage 2: softmax over j, one warp per head.
    {
        int hh = warp;
        float m = -INFINITY;
        for (int j = lane; j < Nn; j += 32)
            m = fmaxf(m, esh[hh * Nn + j]);
        #pragma unroll
        for (int o = 16; o > 0; o >>= 1)
            m = fmaxf(m, __shfl_xor_sync(0xffffffffu, m, o));
        float s = 0.f;
        for (int j = lane; j < Nn; j += 32) {
            float p = __expf(esh[hh * Nn + j] - m);
            esh[hh * Nn + j] = p;
            s += p;
        }
        #pragma unroll
        for (int o = 16; o > 0; o >>= 1)
            s += __shfl_xor_sync(0xffffffffu, s, o);
        if (lane == 0) inv_sh[hh] = 1.f / s;
    }
    __syncthreads();

    // ---- Stage 3: out[b,i,d] = (1/s_h) * sum_j p[h][j] * g[b,j,d], d head h=d>>4.
    // 256 threads: two halves of the j range for ILP.
    {
        int d    = tid & 127;
        int half = tid >> 7;
        int hh   = d >> 4;
        const float* gp = g_buf + (size_t)b * Nn * Dd + d;
        const float* ep = esh + hh * Nn;
        float acc = 0.f;
        int j0 = half * 100;
        #pragma unroll 4
        for (int j = j0; j < j0 + 100; j++)
            acc += ep[j] * gp[(size_t)j * Dd];
        if (half) outp[d] = acc;
        __syncthreads();
        if (!half)
            out[(size_t)row * Dd + d] = (acc + outp[d]) * inv_sh[hh];
    }
}

// ---------------------------------------------------------------------------
extern "C" void kernel_launch(void* const* d_in, const int* in_sizes, int n_in,
                              void* d_out, int out_size)
{
    const float* h   = (const float*)d_in[0];
    const int*   adj = (const int*)  d_in[1];
    const float* dis = (const float*)d_in[2];
    const float* W   = (const float*)d_in[3];
    const float* We  = (const float*)d_in[4];
    const float* a   = (const float*)d_in[5];
    float* out = (float*)d_out;

    precompute_c<<<1, 384>>>(W, We, a);

    size_t smem = (size_t)(Dd * Dd + Dd) * sizeof(float);   // ~66 KB
    cudaFuncSetAttribute(gemm_g, cudaFuncAttributeMaxDynamicSharedMemorySize,
                         (int)smem);
    gemm_g<<<ROWS / 16, 256, smem>>>(h, W);

    attn_kernel<<<ROWS, 256>>>(dis, adj, out);
}

// round 3
// speedup vs baseline: 1.2523x; 1.2523x over previous
#include <cuda_runtime.h>
#include <math.h>

#define Bb 16
#define Nn 200
#define Dd 128
#define Hh 8
#define ROWS (Bb*Nn)          // 3200
#define NEG_SLOPE 0.2f
#define RPB 32                // rows per gemm block

// Scratch (static device globals — no allocation)
__device__ float g_buf[ROWS * Dd];      // g = h @ W           (1.6 MB)
__device__ float si_buf[ROWS * Hh];     // s_i
__device__ float sj_buf[ROWS * Hh];     // s_j
__device__ float c3g[Dd * Hh];          // W_e folded with a3

// ---------------------------------------------------------------------------
// Kernel 0: c3[d][h] = sum_q W_e[d, h*16+q] * a3[q].  8 blocks (one per head).
// ---------------------------------------------------------------------------
__global__ void __launch_bounds__(128) precompute_c3(const float* __restrict__ We,
                                                     const float* __restrict__ a)
{
    __shared__ float a3sh[16];
    int t = threadIdx.x;
    int h = blockIdx.x;
    if (t < 16) a3sh[t] = a[32 + t];
    __syncthreads();
    const float4* row = (const float4*)(We + (size_t)t * Dd + h * 16);
    float s = 0.f;
    #pragma unroll
    for (int qv = 0; qv < 4; qv++) {
        float4 w4 = row[qv];
        s += w4.x * a3sh[qv * 4 + 0] + w4.y * a3sh[qv * 4 + 1]
           + w4.z * a3sh[qv * 4 + 2] + w4.w * a3sh[qv * 4 + 3];
    }
    c3g[t * Hh + h] = s;
}

// ---------------------------------------------------------------------------
// Kernel 1: g = h @ W (register-blocked 4x4), plus c1/c2 (from smem W) and
// s_i, s_j. 100 blocks x 256 threads, 32 rows per block.
// smem: Wsh (stride 132, bank-safe), hT (transposed, stride 36), csh, ash.
// ---------------------------------------------------------------------------
#define WS 132
#define HS 36
__global__ void __launch_bounds__(256) gemm_g(const float* __restrict__ h,
                                              const float* __restrict__ W,
                                              const float* __restrict__ a)
{
    extern __shared__ float smem1[];
    float* Wsh = smem1;                       // 128*132
    float* hT  = Wsh + Dd * WS;               // 128*36
    float* csh = hT + Dd * HS;                // 2*128*8  [which][d][h]
    float* ash = csh + 2 * Dd * Hh;           // 32

    int t = threadIdx.x;
    int row0 = blockIdx.x * RPB;

    if (t < 32) ash[t] = a[t];

    // Stage W (padded) — coalesced global reads.
    for (int idx = t; idx < Dd * Dd; idx += 256)
        Wsh[(idx >> 7) * WS + (idx & 127)] = W[idx];

    // Stage h tile transposed: hT[k][r].
    for (int idx = t; idx < RPB * Dd; idx += 256) {
        int r = idx >> 7, k = idx & 127;
        hT[k * HS + r] = h[(size_t)(row0 + r) * Dd + k];
    }
    __syncthreads();

    // c1/c2 from Wsh: thread -> (which, head, dgrp of 8 d's).
    {
        int which = t >> 7;
        int head  = (t >> 4) & 7;
        int dgrp  = t & 15;
        float s[8] = {0.f, 0.f, 0.f, 0.f, 0.f, 0.f, 0.f, 0.f};
        #pragma unroll
        for (int q = 0; q < 16; q++) {
            float av = ash[which * 16 + q];
            #pragma unroll
            for (int dd = 0; dd < 8; dd++)
                s[dd] += Wsh[(dgrp * 8 + dd) * WS + head * 16 + q] * av;
        }
        #pragma unroll
        for (int dd = 0; dd < 8; dd++)
            csh[(which * Dd + dgrp * 8 + dd) * Hh + head] = s[dd];
    }

    // Main GEMM: thread computes 4 rows x 4 cols.
    int c0 = (t & 31) * 4;
    int r0 = (t >> 5) * 4;
    float acc[4][4];
    #pragma unroll
    for (int i = 0; i < 4; i++)
        #pragma unroll
        for (int j = 0; j < 4; j++) acc[i][j] = 0.f;

    #pragma unroll 4
    for (int k = 0; k < Dd; k++) {
        float4 w4 = *(const float4*)&Wsh[k * WS + c0];
        float4 h4 = *(const float4*)&hT[k * HS + r0];
        float hr[4] = {h4.x, h4.y, h4.z, h4.w};
        float wc[4] = {w4.x, w4.y, w4.z, w4.w};
        #pragma unroll
        for (int i = 0; i < 4; i++)
            #pragma unroll
            for (int j = 0; j < 4; j++)
                acc[i][j] += hr[i] * wc[j];
    }
    #pragma unroll
    for (int i = 0; i < 4; i++)
        *(float4*)&g_buf[(size_t)(row0 + r0 + i) * Dd + c0] =
            make_float4(acc[i][0], acc[i][1], acc[i][2], acc[i][3]);

    __syncthreads();   // csh ready (and hT stable)

    // s_i / s_j: 512 dots of length 128. thread -> (head = t&7, r = (t>>3)&31).
    {
        int head = t & 7;
        int r    = (t >> 3) & 31;
        #pragma unroll
        for (int which = 0; which < 2; which++) {
            float s = 0.f;
            #pragma unroll 8
            for (int k = 0; k < Dd; k++)
                s += hT[k * HS + r] * csh[(which * Dd + k) * Hh + head];
            float* dst = which ? sj_buf : si_buf;
            dst[(row0 + r) * Hh + head] = s;
        }
    }
}

// ---------------------------------------------------------------------------
// Kernel 2: per (b,i): stream dis_mat row-block, compute s_e (8 heads),
// build masked leaky-relu logits, softmax over j, aggregate out = attn @ g.
// Grid = 3200 blocks (one per (b,i)), 256 threads.
// ---------------------------------------------------------------------------
__global__ void __launch_bounds__(256) attn_kernel(const float* __restrict__ dis,
                                                   const int*   __restrict__ adj,
                                                   float*       __restrict__ out)
{
    __shared__ float esh[Hh * Nn];   // [head][j] logits -> unnormalized probs
    __shared__ float si_sh[Hh];
    __shared__ float inv_sh[Hh];
    __shared__ float outp[Dd];

    int tid  = threadIdx.x;
    int lane = tid & 31;
    int warp = tid >> 5;             // 0..7
    int row  = blockIdx.x;           // b*200 + i
    int b    = row / Nn;

    // Per-lane slice of c3: lane covers d = lane*4 .. lane*4+3, all 8 heads.
    float c3r[32];
    {
        const float4* cv = (const float4*)c3g;
        #pragma unroll
        for (int t = 0; t < 8; t++)
            ((float4*)c3r)[t] = cv[lane * 8 + t];
    }
    if (tid < Hh) si_sh[tid] = si_buf[row * Hh + tid];
    __syncthreads();

    // ---- Stage 1: s_e + logits. Warp w handles j = w, w+8, ... (25 rows).
    const float4* disv = (const float4*)dis;
    size_t rb = (size_t)row * Nn;
    for (int jj = warp; jj < Nn; jj += 8) {
        float4 dv = disv[(rb + jj) * 32 + lane];
        float v[8];
        #pragma unroll
        for (int h = 0; h < 8; h++)
            v[h] = dv.x * c3r[h] + dv.y * c3r[8 + h]
                 + dv.z * c3r[16 + h] + dv.w * c3r[24 + h];

        // Head-folding butterfly: 9 shuffles instead of 40.
        float w4[4];
        {
            bool hi = (lane & 16) != 0;
            #pragma unroll
            for (int k = 0; k < 4; k++) {
                float send = hi ? v[k] : v[k + 4];
                float recv = __shfl_xor_sync(0xffffffffu, send, 16);
                w4[k] = (hi ? v[k + 4] : v[k]) + recv;
            }
        }
        float w2[2];
        {
            bool hi = (lane & 8) != 0;
            #pragma unroll
            for (int k = 0; k < 2; k++) {
                float send = hi ? w4[k] : w4[k + 2];
                float recv = __shfl_xor_sync(0xffffffffu, send, 8);
                w2[k] = (hi ? w4[k + 2] : w4[k]) + recv;
            }
        }
        float y;
        {
            bool hi = (lane & 4) != 0;
            float send = hi ? w2[0] : w2[1];
            float recv = __shfl_xor_sync(0xffffffffu, send, 4);
            y = (hi ? w2[1] : w2[0]) + recv;
        }
        y += __shfl_xor_sync(0xffffffffu, y, 1);
        y += __shfl_xor_sync(0xffffffffu, y, 2);

        if ((lane & 3) == 0) {
            int head = lane >> 2;
            float e = si_sh[head]
                    + sj_buf[((size_t)b * Nn + jj) * Hh + head]
                    + y;
            e = (e > 0.f) ? e : NEG_SLOPE * e;          // leaky relu
            if (adj[rb + jj] == 0) e = -INFINITY;       // mask
            esh[head * Nn + jj] = e;
        }
    }
    __syncthreads();

    // ---- Stage 2: softmax over j, one warp per head.
    {
        int hh = warp;
        float m = -INFINITY;
        for (int j = lane; j < Nn; j += 32)
            m = fmaxf(m, esh[hh * Nn + j]);
        #pragma unroll
        for (int o = 16; o > 0; o >>= 1)
            m = fmaxf(m, __shfl_xor_sync(0xffffffffu, m, o));
        float s = 0.f;
        for (int j = lane; j < Nn; j += 32) {
            float p = __expf(esh[hh * Nn + j] - m);
            esh[hh * Nn + j] = p;
            s += p;
        }
        #pragma unroll
        for (int o = 16; o > 0; o >>= 1)
            s += __shfl_xor_sync(0xffffffffu, s, o);
        if (lane == 0) inv_sh[hh] = 1.f / s;
    }
    __syncthreads();

    // ---- Stage 3: out[b,i,d] = (1/s_h) * sum_j p[h][j] * g[b,j,d].
    {
        int d    = tid & 127;
        int half = tid >> 7;
        int hh   = d >> 4;
        const float* gp = g_buf + (size_t)b * Nn * Dd + d;
        const float* ep = esh + hh * Nn;
        float acc = 0.f;
        int j0 = half * 100;
        #pragma unroll 4
        for (int j = j0; j < j0 + 100; j++)
            acc += ep[j] * gp[(size_t)j * Dd];
        if (half) outp[d] = acc;
        __syncthreads();
        if (!half)
            out[(size_t)row * Dd + d] = (acc + outp[d]) * inv_sh[hh];
    }
}

// ---------------------------------------------------------------------------
extern "C" void kernel_launch(void* const* d_in, const int* in_sizes, int n_in,
                              void* d_out, int out_size)
{
    const float* h   = (const float*)d_in[0];
    const int*   adj = (const int*)  d_in[1];
    const float* dis = (const float*)d_in[2];
    const float* W   = (const float*)d_in[3];
    const float* We  = (const float*)d_in[4];
    const float* a   = (const float*)d_in[5];
    float* out = (float*)d_out;

    size_t smem = (size_t)(Dd * WS + Dd * HS + 2 * Dd * Hh + 32) * sizeof(float);
    static bool attr_set = false;
    cudaFuncSetAttribute(gemm_g, cudaFuncAttributeMaxDynamicSharedMemorySize,
                         (int)smem);
    (void)attr_set;

    gemm_g<<<ROWS / RPB, 256, smem>>>(h, W, a);
    precompute_c3<<<Hh, 128>>>(We, a);
    attn_kernel<<<ROWS, 256>>>(dis, adj, out);
}

// round 4
// speedup vs baseline: 1.9915x; 1.5903x over previous
#include <cuda_runtime.h>
#include <math.h>

#define Bb 16
#define Nn 200
#define Dd 128
#define Hh 8
#define ROWS (Bb*Nn)          // 3200
#define NEG_SLOPE 0.2f
#define RPB 16                // rows per gemm block
#define WS 132                // Wsh row stride (floats)
#define HS 20                 // hT row stride (floats)
#define ES 201                // esh row stride (odd -> conflict-free head reads)

// Scratch (static device globals — no allocation)
__device__ float g_buf[ROWS * Dd];      // g = h @ W           (1.6 MB)
__device__ float si_buf[ROWS * Hh];     // s_i
__device__ float sj_buf[ROWS * Hh];     // s_j
__device__ float c3g[Dd * Hh];          // W_e folded with a3

// ---------------------------------------------------------------------------
// Kernel 0: c3[d][h] = sum_q W_e[d, h*16+q] * a3[q].  8 blocks (one per head).
// ---------------------------------------------------------------------------
__global__ void __launch_bounds__(128) precompute_c3(const float* __restrict__ We,
                                                     const float* __restrict__ a)
{
    __shared__ float a3sh[16];
    int t = threadIdx.x;
    int h = blockIdx.x;
    if (t < 16) a3sh[t] = a[32 + t];
    __syncthreads();
    const float4* row = (const float4*)(We + (size_t)t * Dd + h * 16);
    float s = 0.f;
    #pragma unroll
    for (int qv = 0; qv < 4; qv++) {
        float4 w4 = row[qv];
        s += w4.x * a3sh[qv * 4 + 0] + w4.y * a3sh[qv * 4 + 1]
           + w4.z * a3sh[qv * 4 + 2] + w4.w * a3sh[qv * 4 + 3];
    }
    c3g[t * Hh + h] = s;
}

// ---------------------------------------------------------------------------
// Kernel 1: PURE gemm  g = h @ W.  200 blocks x 256 threads, 16 rows/block.
// Thread computes 2 rows x 4 cols. Bank-safe padded smem.
// ---------------------------------------------------------------------------
__global__ void __launch_bounds__(256) gemm_g(const float* __restrict__ h,
                                              const float* __restrict__ W)
{
    extern __shared__ float smem1[];
    float* Wsh = smem1;                       // 128*132
    float* hT  = Wsh + Dd * WS;               // 128*20 (transposed h tile)

    int t = threadIdx.x;
    int row0 = blockIdx.x * RPB;

    #pragma unroll 8
    for (int idx = t; idx < Dd * Dd; idx += 256)
        Wsh[(idx >> 7) * WS + (idx & 127)] = W[idx];

    #pragma unroll 2
    for (int idx = t; idx < RPB * Dd; idx += 256) {
        int r = idx >> 7, k = idx & 127;
        hT[k * HS + r] = h[(size_t)(row0 + r) * Dd + k];
    }
    __syncthreads();

    int c0 = (t & 31) * 4;          // 4 consecutive cols (float4 in Wsh)
    int r0 = (t >> 5) * 2;          // 2 rows (float2 in hT, broadcast in warp)
    float acc0[4] = {0.f, 0.f, 0.f, 0.f};
    float acc1[4] = {0.f, 0.f, 0.f, 0.f};

    #pragma unroll 8
    for (int k = 0; k < Dd; k++) {
        float4 w4 = *(const float4*)&Wsh[k * WS + c0];
        float2 h2 = *(const float2*)&hT[k * HS + r0];
        acc0[0] += h2.x * w4.x;  acc0[1] += h2.x * w4.y;
        acc0[2] += h2.x * w4.z;  acc0[3] += h2.x * w4.w;
        acc1[0] += h2.y * w4.x;  acc1[1] += h2.y * w4.y;
        acc1[2] += h2.y * w4.z;  acc1[3] += h2.y * w4.w;
    }
    *(float4*)&g_buf[(size_t)(row0 + r0)     * Dd + c0] =
        make_float4(acc0[0], acc0[1], acc0[2], acc0[3]);
    *(float4*)&g_buf[(size_t)(row0 + r0 + 1) * Dd + c0] =
        make_float4(acc1[0], acc1[1], acc1[2], acc1[3]);
}

// ---------------------------------------------------------------------------
// Kernel 1b: s_i / s_j from g:  s_{i}[row,h] = g[row, h*16.. ] . a1 (a2 for j).
// 200 blocks x 256 threads; thread -> (row, which, head).
// ---------------------------------------------------------------------------
__global__ void __launch_bounds__(256) s_ij_kernel(const float* __restrict__ a)
{
    __shared__ float ash[32];
    int t = threadIdx.x;
    if (t < 32) ash[t] = a[t];
    __syncthreads();

    int idx   = blockIdx.x * 256 + t;      // < 51200
    int row   = idx >> 4;
    int sub   = idx & 15;
    int which = sub >> 3;
    int head  = sub & 7;

    const float4* gr = (const float4*)(g_buf + (size_t)row * Dd + head * 16);
    const float*  av = ash + which * 16;
    float s = 0.f;
    #pragma unroll
    for (int qv = 0; qv < 4; qv++) {
        float4 g4 = gr[qv];
        s += g4.x * av[qv * 4 + 0] + g4.y * av[qv * 4 + 1]
           + g4.z * av[qv * 4 + 2] + g4.w * av[qv * 4 + 3];
    }
    float* dst = which ? sj_buf : si_buf;
    dst[row * Hh + head] = s;
}

// ---------------------------------------------------------------------------
// Kernel 2: per (b,i): stream dis row-block (MLP=5 prefetch), s_e + logits,
// softmax, out = attn @ g (float4 loads + cross-warp reduce).
// ---------------------------------------------------------------------------
__global__ void __launch_bounds__(256, 3) attn_kernel(const float* __restrict__ dis,
                                                      const int*   __restrict__ adj,
                                                      float*       __restrict__ out)
{
    __shared__ float esh[Hh * ES];       // [head][j], stride 201
    __shared__ float sjsh[Nn * Hh];      // [j][h]
    __shared__ float si_sh[Hh];
    __shared__ float inv_sh[Hh];
    __shared__ float part[Hh][Dd];       // stage-3 partials [warp][d]
    __shared__ int   adjsh[Nn];

    int tid  = threadIdx.x;
    int lane = tid & 31;
    int warp = tid >> 5;                 // 0..7
    int row  = blockIdx.x;               // b*200 + i
    int b    = row / Nn;
    size_t rb = (size_t)row * Nn;

    // Preload sj (batch b, all j/heads), adj row, si.
    for (int idx = tid; idx < Nn * Hh; idx += 256)
        sjsh[idx] = sj_buf[(size_t)b * Nn * Hh + idx];
    for (int idx = tid; idx < Nn; idx += 256)
        adjsh[idx] = adj[rb + idx];
    if (tid < Hh) si_sh[tid] = si_buf[row * Hh + tid];

    // Per-lane slice of c3: lane covers d = lane*4..+3, all 8 heads.
    float c3r[32];
    {
        const float4* cv = (const float4*)c3g;
        #pragma unroll
        for (int t2 = 0; t2 < 8; t2++)
            ((float4*)c3r)[t2] = cv[lane * 8 + t2];
    }
    __syncthreads();

    // ---- Stage 1: s_e + logits. Warp w: j = w + 8t, t=0..24, chunks of 5.
    const float4* disv = (const float4*)dis;
    for (int c = 0; c < 5; c++) {
        float4 dv[5];
        #pragma unroll
        for (int u = 0; u < 5; u++) {
            int jj = warp + 8 * (c * 5 + u);
            dv[u] = disv[(rb + jj) * 32 + lane];
        }
        #pragma unroll
        for (int u = 0; u < 5; u++) {
            int jj = warp + 8 * (c * 5 + u);
            float v[8];
            #pragma unroll
            for (int h = 0; h < 8; h++)
                v[h] = dv[u].x * c3r[h]      + dv[u].y * c3r[8 + h]
                     + dv[u].z * c3r[16 + h] + dv[u].w * c3r[24 + h];

            // Head-folding butterfly: lane (h*4) ends with head h's total.
            float w4[4];
            {
                bool hi = (lane & 16) != 0;
                #pragma unroll
                for (int k = 0; k < 4; k++) {
                    float send = hi ? v[k] : v[k + 4];
                    float recv = __shfl_xor_sync(0xffffffffu, send, 16);
                    w4[k] = (hi ? v[k + 4] : v[k]) + recv;
                }
            }
            float w2[2];
            {
                bool hi = (lane & 8) != 0;
                #pragma unroll
                for (int k = 0; k < 2; k++) {
                    float send = hi ? w4[k] : w4[k + 2];
                    float recv = __shfl_xor_sync(0xffffffffu, send, 8);
                    w2[k] = (hi ? w4[k + 2] : w4[k]) + recv;
                }
            }
            float y;
            {
                bool hi = (lane & 4) != 0;
                float send = hi ? w2[0] : w2[1];
                float recv = __shfl_xor_sync(0xffffffffu, send, 4);
                y = (hi ? w2[1] : w2[0]) + recv;
            }
            y += __shfl_xor_sync(0xffffffffu, y, 1);
            y += __shfl_xor_sync(0xffffffffu, y, 2);

            if ((lane & 3) == 0) {
                int head = lane >> 2;
                float e = si_sh[head] + sjsh[jj * Hh + head] + y;
                e = (e > 0.f) ? e : NEG_SLOPE * e;          // leaky relu
                if (adjsh[jj] == 0) e = -INFINITY;          // mask
                esh[head * ES + jj] = e;
            }
        }
    }
    __syncthreads();

    // ---- Stage 2: softmax over j, one warp per head.
    {
        int hh = warp;
        float m = -INFINITY;
        for (int j = lane; j < Nn; j += 32)
            m = fmaxf(m, esh[hh * ES + j]);
        #pragma unroll
        for (int o = 16; o > 0; o >>= 1)
            m = fmaxf(m, __shfl_xor_sync(0xffffffffu, m, o));
        float s = 0.f;
        for (int j = lane; j < Nn; j += 32) {
            float p = __expf(esh[hh * ES + j] - m);
            esh[hh * ES + j] = p;
            s += p;
        }
        #pragma unroll
        for (int o = 16; o > 0; o >>= 1)
            s += __shfl_xor_sync(0xffffffffu, s, o);
        if (lane == 0) inv_sh[hh] = 1.f / s;
    }
    __syncthreads();

    // ---- Stage 3: out[d] = (1/s) * sum_j p[h(d)][j] * g[b,j,d].
    // Warp w: j = w + 8t; lane covers d = lane*4..+3 (head = lane>>2).
    {
        const float4* gvec = (const float4*)g_buf;
        size_t gb = (size_t)b * Nn;
        int myh = lane >> 2;
        float ax = 0.f, ay = 0.f, az = 0.f, aw = 0.f;
        for (int c = 0; c < 5; c++) {
            float4 gv[5]; float p[5];
            #pragma unroll
            for (int u = 0; u < 5; u++) {
                int jj = warp + 8 * (c * 5 + u);
                gv[u] = gvec[(gb + jj) * 32 + lane];
                p[u]  = esh[myh * ES + jj];
            }
            #pragma unroll
            for (int u = 0; u < 5; u++) {
                ax += p[u] * gv[u].x;  ay += p[u] * gv[u].y;
                az += p[u] * gv[u].z;  aw += p[u] * gv[u].w;
            }
        }
        *(float4*)&part[warp][lane * 4] = make_float4(ax, ay, az, aw);
        __syncthreads();
        if (tid < Dd) {
            int d = tid;
            float s = 0.f;
            #pragma unroll
            for (int w = 0; w < Hh; w++) s += part[w][d];
            out[(size_t)row * Dd + d] = s * inv_sh[d >> 4];
        }
    }
}

// ---------------------------------------------------------------------------
extern "C" void kernel_launch(void* const* d_in, const int* in_sizes, int n_in,
                              void* d_out, int out_size)
{
    const float* h   = (const float*)d_in[0];
    const int*   adj = (const int*)  d_in[1];
    const float* dis = (const float*)d_in[2];
    const float* W   = (const float*)d_in[3];
    const float* We  = (const float*)d_in[4];
    const float* a   = (const float*)d_in[5];
    float* out = (float*)d_out;

    size_t smem = (size_t)(Dd * WS + Dd * HS) * sizeof(float);   // ~78 KB
    cudaFuncSetAttribute(gemm_g, cudaFuncAttributeMaxDynamicSharedMemorySize,
                         (int)smem);

    gemm_g<<<ROWS / RPB, 256, smem>>>(h, W);
    s_ij_kernel<<<ROWS * 16 / 256, 256>>>(a);
    precompute_c3<<<Hh, 128>>>(We, a);
    attn_kernel<<<ROWS, 256>>>(dis, adj, out);
}

// round 5
// speedup vs baseline: 2.0932x; 1.0511x over previous
#include <cuda_runtime.h>
#include <math.h>

#define Bb 16
#define Nn 200
#define Dd 128
#define Hh 8
#define ROWS (Bb*Nn)          // 3200
#define NEG_SLOPE 0.2f
#define RPB 16                // rows per gemm block
#define WS 132                // Wsh row stride (floats)
#define HS 20                 // hT row stride (floats)
#define ES 201                // esh row stride (odd -> conflict-free head reads)

// Scratch (static device globals — no allocation)
__device__ float g_buf[ROWS * Dd];      // g = h @ W           (1.6 MB)
__device__ float si_buf[ROWS * Hh];     // s_i
__device__ float sj_buf[ROWS * Hh];     // s_j
__device__ float c3g[Dd * Hh];          // W_e folded with a3

// ---------------------------------------------------------------------------
// Kernel 1: PURE gemm  g = h @ W.  200 blocks x 256 threads, 16 rows/block.
// Thread computes 2 rows x 4 cols. Bank-safe padded smem. float4 staging.
// ---------------------------------------------------------------------------
__global__ void __launch_bounds__(256) gemm_g(const float* __restrict__ h,
                                              const float* __restrict__ W)
{
    extern __shared__ float smem1[];
    float* Wsh = smem1;                       // 128*132
    float* hT  = Wsh + Dd * WS;               // 128*20 (transposed h tile)

    int t = threadIdx.x;
    int row0 = blockIdx.x * RPB;

    // Stage W: vectorized global reads, padded smem stores.
    {
        const float4* Wv = (const float4*)W;
        #pragma unroll 4
        for (int idx = t; idx < Dd * Dd / 4; idx += 256) {
            float4 w4 = Wv[idx];
            int r = idx >> 5;          // row (32 float4 per row)
            int c = (idx & 31) * 4;
            *(float4*)&Wsh[r * WS + c] = w4;
        }
    }
    #pragma unroll 2
    for (int idx = t; idx < RPB * Dd; idx += 256) {
        int r = idx >> 7, k = idx & 127;
        hT[k * HS + r] = h[(size_t)(row0 + r) * Dd + k];
    }
    __syncthreads();

    int c0 = (t & 31) * 4;          // 4 consecutive cols (float4 in Wsh)
    int r0 = (t >> 5) * 2;          // 2 rows (float2 in hT)
    float acc0[4] = {0.f, 0.f, 0.f, 0.f};
    float acc1[4] = {0.f, 0.f, 0.f, 0.f};

    #pragma unroll 8
    for (int k = 0; k < Dd; k++) {
        float4 w4 = *(const float4*)&Wsh[k * WS + c0];
        float2 h2 = *(const float2*)&hT[k * HS + r0];
        acc0[0] += h2.x * w4.x;  acc0[1] += h2.x * w4.y;
        acc0[2] += h2.x * w4.z;  acc0[3] += h2.x * w4.w;
        acc1[0] += h2.y * w4.x;  acc1[1] += h2.y * w4.y;
        acc1[2] += h2.y * w4.z;  acc1[3] += h2.y * w4.w;
    }
    *(float4*)&g_buf[(size_t)(row0 + r0)     * Dd + c0] =
        make_float4(acc0[0], acc0[1], acc0[2], acc0[3]);
    *(float4*)&g_buf[(size_t)(row0 + r0 + 1) * Dd + c0] =
        make_float4(acc1[0], acc1[1], acc1[2], acc1[3]);
}

// ---------------------------------------------------------------------------
// Kernel 1b (fused): blocks 0..199 -> s_i/s_j from g; blocks 200..207 -> c3.
// ---------------------------------------------------------------------------
__global__ void __launch_bounds__(256) sij_c3_kernel(const float* __restrict__ a,
                                                     const float* __restrict__ We)
{
    __shared__ float ash[48];
    int t = threadIdx.x;
    if (t < 48) ash[t] = a[t];
    __syncthreads();

    if (blockIdx.x < 200) {
        int idx   = blockIdx.x * 256 + t;      // < 51200
        int row   = idx >> 4;
        int sub   = idx & 15;
        int which = sub >> 3;
        int head  = sub & 7;

        const float4* gr = (const float4*)(g_buf + (size_t)row * Dd + head * 16);
        const float*  av = ash + which * 16;
        float s = 0.f;
        #pragma unroll
        for (int qv = 0; qv < 4; qv++) {
            float4 g4 = gr[qv];
            s += g4.x * av[qv * 4 + 0] + g4.y * av[qv * 4 + 1]
               + g4.z * av[qv * 4 + 2] + g4.w * av[qv * 4 + 3];
        }
        float* dst = which ? sj_buf : si_buf;
        dst[row * Hh + head] = s;
    } else {
        // c3[d][h] = sum_q W_e[d, h*16+q] * a3[q]; block handles one head.
        int h = blockIdx.x - 200;
        if (t < Dd) {
            const float4* row = (const float4*)(We + (size_t)t * Dd + h * 16);
            const float*  av  = ash + 32;
            float s = 0.f;
            #pragma unroll
            for (int qv = 0; qv < 4; qv++) {
                float4 w4 = row[qv];
                s += w4.x * av[qv * 4 + 0] + w4.y * av[qv * 4 + 1]
                   + w4.z * av[qv * 4 + 2] + w4.w * av[qv * 4 + 3];
            }
            c3g[t * Hh + h] = s;
        }
    }
}

// ---------------------------------------------------------------------------
// Kernel 2: per (b,i): stream dis row-block (depth-4 prefetch), s_e + logits,
// softmax, out = attn @ g.  4 blocks/SM target (<=64 regs).
// ---------------------------------------------------------------------------
__device__ __forceinline__ void process_j(float4 dv, int jj, int lane,
                                          const float* c3r,
                                          const float* si_sh,
                                          const float* sjsh,
                                          const int*   adjsh,
                                          float*       esh)
{
    float v[8];
    #pragma unroll
    for (int h = 0; h < 8; h++)
        v[h] = dv.x * c3r[h]      + dv.y * c3r[8 + h]
             + dv.z * c3r[16 + h] + dv.w * c3r[24 + h];

    // Head-folding butterfly: lane (h*4) ends with head h's total (9 shfl).
    float w4[4];
    {
        bool hi = (lane & 16) != 0;
        #pragma unroll
        for (int k = 0; k < 4; k++) {
            float send = hi ? v[k] : v[k + 4];
            float recv = __shfl_xor_sync(0xffffffffu, send, 16);
            w4[k] = (hi ? v[k + 4] : v[k]) + recv;
        }
    }
    float w2[2];
    {
        bool hi = (lane & 8) != 0;
        #pragma unroll
        for (int k = 0; k < 2; k++) {
            float send = hi ? w4[k] : w4[k + 2];
            float recv = __shfl_xor_sync(0xffffffffu, send, 8);
            w2[k] = (hi ? w4[k + 2] : w4[k]) + recv;
        }
    }
    float y;
    {
        bool hi = (lane & 4) != 0;
        float send = hi ? w2[0] : w2[1];
        float recv = __shfl_xor_sync(0xffffffffu, send, 4);
        y = (hi ? w2[1] : w2[0]) + recv;
    }
    y += __shfl_xor_sync(0xffffffffu, y, 1);
    y += __shfl_xor_sync(0xffffffffu, y, 2);

    if ((lane & 3) == 0) {
        int head = lane >> 2;
        float e = si_sh[head] + sjsh[jj * Hh + head] + y;
        e = (e > 0.f) ? e : NEG_SLOPE * e;          // leaky relu
        if (adjsh[jj] == 0) e = -INFINITY;          // mask
        esh[head * ES + jj] = e;
    }
}

__global__ void __launch_bounds__(256, 4) attn_kernel(const float* __restrict__ dis,
                                                      const int*   __restrict__ adj,
                                                      float*       __restrict__ out)
{
    __shared__ float esh[Hh * ES];       // [head][j], stride 201
    __shared__ float sjsh[Nn * Hh];      // [j][h]
    __shared__ float si_sh[Hh];
    __shared__ float inv_sh[Hh];
    __shared__ float part[Hh][Dd];       // stage-3 partials [warp][d]
    __shared__ int   adjsh[Nn];

    int tid  = threadIdx.x;
    int lane = tid & 31;
    int warp = tid >> 5;                 // 0..7
    int row  = blockIdx.x;               // b*200 + i
    int b    = row / Nn;
    size_t rb = (size_t)row * Nn;

    // Preload sj (batch b, all j/heads), adj row, si.
    for (int idx = tid; idx < Nn * Hh; idx += 256)
        sjsh[idx] = sj_buf[(size_t)b * Nn * Hh + idx];
    for (int idx = tid; idx < Nn; idx += 256)
        adjsh[idx] = adj[rb + idx];
    if (tid < Hh) si_sh[tid] = si_buf[row * Hh + tid];

    // Per-lane slice of c3: lane covers d = lane*4..+3, all 8 heads.
    float c3r[32];
    {
        const float4* cv = (const float4*)c3g;
        #pragma unroll
        for (int t2 = 0; t2 < 8; t2++)
            ((float4*)c3r)[t2] = cv[lane * 8 + t2];
    }
    __syncthreads();

    // ---- Stage 1: warp w handles j = w + 8t, t = 0..24. Chunks of 4 + tail.
    const float4* disv = (const float4*)dis;
    for (int c = 0; c < 6; c++) {
        float4 dv[4];
        #pragma unroll
        for (int u = 0; u < 4; u++)
            dv[u] = disv[(rb + warp + 8 * (c * 4 + u)) * 32 + lane];
        #pragma unroll
        for (int u = 0; u < 4; u++)
            process_j(dv[u], warp + 8 * (c * 4 + u), lane,
                      c3r, si_sh, sjsh, adjsh, esh);
    }
    {
        float4 dv = disv[(rb + warp + 192) * 32 + lane];
        process_j(dv, warp + 192, lane, c3r, si_sh, sjsh, adjsh, esh);
    }
    __syncthreads();

    // ---- Stage 2: softmax over j, one warp per head.
    {
        int hh = warp;
        float m = -INFINITY;
        for (int j = lane; j < Nn; j += 32)
            m = fmaxf(m, esh[hh * ES + j]);
        #pragma unroll
        for (int o = 16; o > 0; o >>= 1)
            m = fmaxf(m, __shfl_xor_sync(0xffffffffu, m, o));
        float s = 0.f;
        for (int j = lane; j < Nn; j += 32) {
            float p = __expf(esh[hh * ES + j] - m);
            esh[hh * ES + j] = p;
            s += p;
        }
        #pragma unroll
        for (int o = 16; o > 0; o >>= 1)
            s += __shfl_xor_sync(0xffffffffu, s, o);
        if (lane == 0) inv_sh[hh] = 1.f / s;
    }
    __syncthreads();

    // ---- Stage 3: out[d] = (1/s) * sum_j p[h(d)][j] * g[b,j,d].
    // Warp w: j = w + 8t; lane covers d = lane*4..+3 (head = lane>>2).
    {
        const float4* gvec = (const float4*)g_buf;
        size_t gb = (size_t)b * Nn;
        int myh = lane >> 2;
        float ax = 0.f, ay = 0.f, az = 0.f, aw = 0.f;
        for (int c = 0; c < 6; c++) {
            float4 gv[4]; float p[4];
            #pragma unroll
            for (int u = 0; u < 4; u++) {
                int jj = warp + 8 * (c * 4 + u);
                gv[u] = gvec[(gb + jj) * 32 + lane];
                p[u]  = esh[myh * ES + jj];
            }
            #pragma unroll
            for (int u = 0; u < 4; u++) {
                ax += p[u] * gv[u].x;  ay += p[u] * gv[u].y;
                az += p[u] * gv[u].z;  aw += p[u] * gv[u].w;
            }
        }
        {
            int jj = warp + 192;
            float4 gv = gvec[(gb + jj) * 32 + lane];
            float  p  = esh[myh * ES + jj];
            ax += p * gv.x;  ay += p * gv.y;  az += p * gv.z;  aw += p * gv.w;
        }
        *(float4*)&part[warp][lane * 4] = make_float4(ax, ay, az, aw);
        __syncthreads();
        if (tid < Dd) {
            int d = tid;
            float s = 0.f;
            #pragma unroll
            for (int w = 0; w < Hh; w++) s += part[w][d];
            out[(size_t)row * Dd + d] = s * inv_sh[d >> 4];
        }
    }
}

// ---------------------------------------------------------------------------
extern "C" void kernel_launch(void* const* d_in, const int* in_sizes, int n_in,
                              void* d_out, int out_size)
{
    const float* h   = (const float*)d_in[0];
    const int*   adj = (const int*)  d_in[1];
    const float* dis = (const float*)d_in[2];
    const float* W   = (const float*)d_in[3];
    const float* We  = (const float*)d_in[4];
    const float* a   = (const float*)d_in[5];
    float* out = (float*)d_out;

    size_t smem = (size_t)(Dd * WS + Dd * HS) * sizeof(float);   // ~78 KB
    cudaFuncSetAttribute(gemm_g, cudaFuncAttributeMaxDynamicSharedMemorySize,
                         (int)smem);

    gemm_g<<<ROWS / RPB, 256, smem>>>(h, W);
    sij_c3_kernel<<<208, 256>>>(a, We);
    attn_kernel<<<ROWS, 256>>>(dis, adj, out);
}